// round 16
// baseline (speedup 1.0000x reference)
#include <cuda_runtime.h>
#include <cuda_bf16.h>
#include <cstdint>

#define N_NODES 50000
#define N_EDGES 800000
#define F 128
#define LN_EPS 1e-5f
#define NBLK 196            // (N_NODES+255)/256
#define NPAD (N_NODES + 128)
#define SROWB 512           // bytes per split row (8 chunks x [32B hi | 32B lo])
#define CSR_BLOCKS 592      // 4 per SM; co-resident for grid barrier
#define GB 391              // GEMM tiles: (N_NODES+127)/128

#define PITCHB 80
#define CHK (128 * PITCHB)           // one K-16 chunk tile (10240 B)
#define SMB_BASE (4 * CHK)
#define SPARAM_OFF (8 * CHK)
#define DYN_TOTAL (SPARAM_OFF + 512)

// ---------------- scratch (__device__ globals only) ----------------
__device__ int   g_is64;
__device__ int   g_count[N_NODES];
__device__ int   g_start[N_NODES + 1];
__device__ int   g_cursor[N_NODES];
__device__ int   g_bsum[NBLK];
__device__ int   g_boff[NBLK];
__device__ int   g_esrc[N_EDGES];
__device__ float g_invdeg[N_NODES];
__device__ char  g_ws[5 * 65536];                    // split weights (tile layout)
__device__ char  g_xs[(size_t)NPAD * SROWB];         // split x
__device__ char  g_ms[(size_t)NPAD * SROWB];         // split neighbor-mean
__device__ float g_h[(size_t)NPAD * F];              // skip out, then layer-1 input
__device__ float g_o[(size_t)NPAD * F];              // raw SAGE out (pre-LN)
__device__ float g_stats[8];
__device__ int   g_barcnt, g_barphase;               // csr barrier

// ---------------- helpers ----------------
__device__ __forceinline__ uint32_t s2u(const void* p) {
    uint32_t a;
    asm("{ .reg .u64 t; cvta.to.shared.u64 t, %1; cvt.u32.u64 %0, t; }"
        : "=r"(a) : "l"(p));
    return a;
}
__device__ __forceinline__ uint32_t pkbf(float a, float b) {
    uint32_t r;
    asm("cvt.rn.bf16x2.f32 %0, %1, %2;" : "=r"(r) : "f"(b), "f"(a));
    return r;
}
__device__ __forceinline__ void ldsm4(uint32_t addr, uint32_t* r) {
    asm volatile("ldmatrix.sync.aligned.m8n8.x4.shared.b16 {%0,%1,%2,%3}, [%4];"
                 : "=r"(r[0]), "=r"(r[1]), "=r"(r[2]), "=r"(r[3]) : "r"(addr));
}
__device__ __forceinline__ void bmma(float* d, const uint32_t* a, uint32_t b0, uint32_t b1) {
    asm volatile("mma.sync.aligned.m16n8k16.row.col.f32.bf16.bf16.f32 "
                 "{%0,%1,%2,%3}, {%4,%5,%6,%7}, {%8,%9}, {%0,%1,%2,%3};"
                 : "+f"(d[0]), "+f"(d[1]), "+f"(d[2]), "+f"(d[3])
                 : "r"(a[0]), "r"(a[1]), "r"(a[2]), "r"(a[3]), "r"(b0), "r"(b1));
}
__device__ __forceinline__ void split4(float4 v, uint2& hi, uint2& lo) {
    float h0 = __bfloat162float(__float2bfloat16_rn(v.x));
    float h1 = __bfloat162float(__float2bfloat16_rn(v.y));
    float h2 = __bfloat162float(__float2bfloat16_rn(v.z));
    float h3 = __bfloat162float(__float2bfloat16_rn(v.w));
    hi = make_uint2(pkbf(h0, h1), pkbf(h2, h3));
    lo = make_uint2(pkbf(v.x - h0, v.y - h1), pkbf(v.z - h2, v.w - h3));
}
__device__ __forceinline__ int ld_idx(const void* ei, long long pos, int is64) {
    if (is64) return (int)((const long long*)ei)[pos];
    return ((const int*)ei)[pos];
}
__device__ __forceinline__ void gridbar(int ph) {
    __syncthreads();
    if (threadIdx.x == 0) {
        __threadfence();
        int v = atomicAdd(&g_barcnt, 1) + 1;
        if (v == CSR_BLOCKS * ph) atomicExch(&g_barphase, ph);
        while (atomicAdd(&g_barphase, 0) < ph) __nanosleep(32);
    }
    __syncthreads();
}
// warp-reduce two floats, lane0 atomically accumulates
__device__ __forceinline__ void warp_stats(float lsum, float lsq, float* s0, float* s1, int lane) {
#pragma unroll
    for (int off = 16; off > 0; off >>= 1) {
        lsum += __shfl_xor_sync(0xffffffffu, lsum, off);
        lsq  += __shfl_xor_sync(0xffffffffu, lsq, off);
    }
    if (lane == 0) {
        atomicAdd(s0, lsum);
        atomicAdd(s1, lsq);
    }
}

// x-split / w-split helpers
__device__ __forceinline__ void do_xsplit(const float* __restrict__ x, int t) {
    int row = t >> 5, lane = t & 31;
    float4 v = *(const float4*)(x + (size_t)row * F + lane * 4);
    uint2 hi, lo;
    split4(v, hi, lo);
    char* dst = g_xs + (size_t)row * SROWB + (lane >> 2) * 64 + (lane & 3) * 8;
    *(uint2*)dst = hi;
    *(uint2*)(dst + 32) = lo;
}
__device__ __forceinline__ void do_wsplit(const float* __restrict__ W0, const float* __restrict__ W1,
                                          const float* __restrict__ W2, const float* __restrict__ W3,
                                          const float* __restrict__ W4, int t) {
    int mat = t >> 12;
    int rem = t & 4095;
    int row = rem >> 5, lane = rem & 31;
    const float* W = (mat == 0) ? W0 : (mat == 1) ? W1 : (mat == 2) ? W2
                     : (mat == 3) ? W3 : W4;
    float4 v = *(const float4*)(W + row * F + lane * 4);
    uint2 hi, lo;
    split4(v, hi, lo);
    char* dst = g_ws + (size_t)mat * 65536 + row * SROWB + (lane >> 2) * 64 + (lane & 3) * 8;
    *(uint2*)dst = hi;
    *(uint2*)(dst + 32) = lo;
}

// ---------------- prep0: zero counters + dtype probe + barrier reset --------
__global__ void prep0_kernel(const void* ei) {
    int i = blockIdx.x * blockDim.x + threadIdx.x;
    if (i < N_NODES) { g_count[i] = 0; g_cursor[i] = 0; }
    if (blockIdx.x == 0) {
        __shared__ int nz;
        int tid = threadIdx.x;
        if (tid == 0) nz = 0;
        __syncthreads();
        int v = ((const int*)ei)[2 * tid + 1];
        if (v != 0) atomicAdd(&nz, 1);
        __syncthreads();
        if (tid == 0) {
            g_is64 = (nz == 0) ? 1 : 0;
            g_barcnt = 0; g_barphase = 0;
        }
        if (tid < 8) g_stats[tid] = 0.0f;
    }
}

// ---------------- persistent CSR build + overlapped pre-splits --------------
__global__ void __launch_bounds__(256) csr_kernel(
    const void* ei, const float* __restrict__ x,
    const float* __restrict__ W0, const float* __restrict__ W1,
    const float* __restrict__ W2, const float* __restrict__ W3,
    const float* __restrict__ W4) {
    __shared__ int sh[256];
    int tid = threadIdx.x;
    int b = blockIdx.x;
    int is64 = g_is64;

    // phase 0: x-split + w-split + histogram (independent work streams)
    for (int t = b * 256 + tid; t < N_NODES * 32; t += CSR_BLOCKS * 256)
        do_xsplit(x, t);
    for (int t = b * 256 + tid; t < 5 * 4096; t += CSR_BLOCKS * 256)
        do_wsplit(W0, W1, W2, W3, W4, t);
    for (int e = b * 256 + tid; e < N_EDGES; e += CSR_BLOCKS * 256) {
        int d = ld_idx(ei, (long long)N_EDGES + e, is64);
        atomicAdd(&g_count[d], 1);
    }
    gridbar(1);

    if (b < NBLK) {
        int i = b * 256 + tid;
        int c = (i < N_NODES) ? g_count[i] : 0;
        sh[tid] = c;
        __syncthreads();
#pragma unroll
        for (int s = 128; s > 0; s >>= 1) {
            if (tid < s) sh[tid] += sh[tid + s];
            __syncthreads();
        }
        if (tid == 0) g_bsum[b] = sh[0];
    }
    gridbar(2);

    if (b == 0) {
        int v = (tid < NBLK) ? g_bsum[tid] : 0;
        sh[tid] = v;
        __syncthreads();
#pragma unroll
        for (int off = 1; off < 256; off <<= 1) {
            int u = (tid >= off) ? sh[tid - off] : 0;
            __syncthreads();
            sh[tid] += u;
            __syncthreads();
        }
        if (tid < NBLK) g_boff[tid] = sh[tid] - v;
        if (tid == 0) g_start[N_NODES] = N_EDGES;
    }
    gridbar(3);

    if (b < NBLK) {
        int i = b * 256 + tid;
        int c = (i < N_NODES) ? g_count[i] : 0;
        sh[tid] = c;
        __syncthreads();
#pragma unroll
        for (int off = 1; off < 256; off <<= 1) {
            int u = (tid >= off) ? sh[tid - off] : 0;
            __syncthreads();
            sh[tid] += u;
            __syncthreads();
        }
        if (i < N_NODES) {
            g_start[i] = sh[tid] - c + g_boff[b];
            g_invdeg[i] = 1.0f / fmaxf((float)c, 1.0f);
        }
    }
    gridbar(4);

    for (int e = b * 256 + tid; e < N_EDGES; e += CSR_BLOCKS * 256) {
        int d = ld_idx(ei, (long long)N_EDGES + e, is64);
        int s = ld_idx(ei, (long long)e, is64);
        int pos = atomicAdd(&g_cursor[d], 1);
        g_esrc[g_start[d] + pos] = s;
    }
}

// ---------------- gather-mean: warp per node, emits split form ----------------
__global__ void gather_kernel(const float* __restrict__ hin) {
    const float* h = hin ? hin : (const float*)g_h;
    int n = (blockIdx.x * blockDim.x + threadIdx.x) >> 5;
    int lane = threadIdx.x & 31;
    if (n >= N_NODES) return;
    int e = g_start[n];
    int end = g_start[n + 1];
    float4 acc0 = make_float4(0.f, 0.f, 0.f, 0.f);
    float4 acc1 = make_float4(0.f, 0.f, 0.f, 0.f);
    for (; e + 1 < end; e += 2) {
        int s0 = g_esrc[e];
        int s1 = g_esrc[e + 1];
        float4 v0 = *(const float4*)(h + (size_t)s0 * F + lane * 4);
        float4 v1 = *(const float4*)(h + (size_t)s1 * F + lane * 4);
        acc0.x += v0.x; acc0.y += v0.y; acc0.z += v0.z; acc0.w += v0.w;
        acc1.x += v1.x; acc1.y += v1.y; acc1.z += v1.z; acc1.w += v1.w;
    }
    if (e < end) {
        int s0 = g_esrc[e];
        float4 v0 = *(const float4*)(h + (size_t)s0 * F + lane * 4);
        acc0.x += v0.x; acc0.y += v0.y; acc0.z += v0.z; acc0.w += v0.w;
    }
    float id = g_invdeg[n];
    acc0.x = (acc0.x + acc1.x) * id;
    acc0.y = (acc0.y + acc1.y) * id;
    acc0.z = (acc0.z + acc1.z) * id;
    acc0.w = (acc0.w + acc1.w) * id;
    uint2 hi, lo;
    split4(acc0, hi, lo);
    char* dst = g_ms + (size_t)n * SROWB + (lane >> 2) * 64 + (lane & 3) * 8;
    *(uint2*)dst = hi;
    *(uint2*)(dst + 32) = lo;
}

// ---------------- compute macro: one K-16 chunk from smem tile --------------
#define CHUNK_MMA(Ab, Bb)                                                      \
    {                                                                          \
        uint32_t aaddr0 = (Ab) + (m0 + rsel) * PITCHB + kb;                    \
        uint32_t aaddr1 = aaddr0 + 16 * PITCHB;                                \
        uint32_t baddr0 = (Bb) + (n0 + rsel) * PITCHB + kb;                    \
        uint32_t baddr1 = baddr0 + 16 * PITCHB;                                \
        uint32_t ahi[2][4], alo[2][4], bhi[2][4], blo[2][4];                   \
        ldsm4(aaddr0, ahi[0]);  ldsm4(aaddr1, ahi[1]);                         \
        ldsm4(baddr0, bhi[0]);  ldsm4(baddr1, bhi[1]);                         \
        ldsm4(aaddr0 + 32, alo[0]);  ldsm4(aaddr1 + 32, alo[1]);               \
        ldsm4(baddr0 + 32, blo[0]);  ldsm4(baddr1 + 32, blo[1]);               \
        _Pragma("unroll")                                                      \
        for (int mt = 0; mt < 2; mt++)                                         \
            _Pragma("unroll")                                                  \
            for (int nt = 0; nt < 4; nt++)                                     \
                bmma(acc[mt][nt], ahi[mt], bhi[nt >> 1][nt & 1],               \
                     bhi[nt >> 1][(nt & 1) + 2]);                              \
        _Pragma("unroll")                                                      \
        for (int mt = 0; mt < 2; mt++)                                         \
            _Pragma("unroll")                                                  \
            for (int nt = 0; nt < 4; nt++)                                     \
                bmma(acc[mt][nt], ahi[mt], blo[nt >> 1][nt & 1],               \
                     blo[nt >> 1][(nt & 1) + 2]);                              \
        _Pragma("unroll")                                                      \
        for (int mt = 0; mt < 2; mt++)                                         \
            _Pragma("unroll")                                                  \
            for (int nt = 0; nt < 4; nt++)                                     \
                bmma(acc[mt][nt], alo[mt], bhi[nt >> 1][nt & 1],               \
                     bhi[nt >> 1][(nt & 1) + 2]);                              \
    }

// ---------------- combined GEMM: SAGE0 (stats) + skip GEMM in one grid ------
__global__ void __launch_bounds__(512) combogemm_kernel(const float* __restrict__ bias)
{
    extern __shared__ __align__(16) char dyn[];
    float* sparam = (float*)(dyn + SPARAM_OFF);

    int tid = threadIdx.x;
    int lane = tid & 31;
    int w = tid >> 5;
    bool skip = blockIdx.x >= GB;
    int row0 = (skip ? blockIdx.x - GB : blockIdx.x) * 128;
    int NP = skip ? 4 : 8;
    float* out = skip ? (float*)g_h : (float*)g_o;

    if (tid < F) sparam[tid] = bias[tid];

    int srow = tid >> 2;
    int q = tid & 3;
    size_t arow512 = (size_t)(row0 + srow) * SROWB;
    size_t brow512 = (size_t)srow * SROWB;

    float acc[2][4][4];
#pragma unroll
    for (int i = 0; i < 2; i++)
#pragma unroll
        for (int j = 0; j < 4; j++)
#pragma unroll
            for (int k = 0; k < 4; k++) acc[i][j][k] = 0.0f;

    uint4 ava, avb, bva, bvb;

#define CLD2(c)                                                                \
    {                                                                          \
        int p = (c);                                                           \
        const char* ap;                                                        \
        int widx, wcb;                                                         \
        if (skip) { ap = g_xs + arow512 + p * 128; widx = 2; wcb = p * 2; }    \
        else if (p < 4) { ap = g_ms + arow512 + p * 128; widx = 0; wcb = p * 2; } \
        else { ap = g_xs + arow512 + (p - 4) * 128; widx = 1; wcb = (p - 4) * 2; } \
        ava = *(const uint4*)(ap + q * 16);                                    \
        avb = *(const uint4*)(ap + 64 + q * 16);                               \
        const char* bp = g_ws + (size_t)widx * 65536 + brow512 + wcb * 64;     \
        bva = *(const uint4*)(bp + q * 16);                                    \
        bvb = *(const uint4*)(bp + 64 + q * 16);                               \
    }

#define CST2(b)                                                                \
    {                                                                          \
        *(uint4*)(dyn + ((b) * 2 + 0) * CHK + srow * PITCHB + q * 16) = ava;   \
        *(uint4*)(dyn + ((b) * 2 + 1) * CHK + srow * PITCHB + q * 16) = avb;   \
        *(uint4*)(dyn + SMB_BASE + ((b) * 2 + 0) * CHK + srow * PITCHB + q * 16) = bva; \
        *(uint4*)(dyn + SMB_BASE + ((b) * 2 + 1) * CHK + srow * PITCHB + q * 16) = bvb; \
    }

    CLD2(0);
    CST2(0);
    __syncthreads();

    int wm = w >> 2, wn = w & 3;
    int m0 = wm * 32, n0 = wn * 32;
    uint32_t rsel = (uint32_t)(lane & 15);
    uint32_t kb = (uint32_t)((lane >> 4) * 16);

    for (int c = 0; c < NP; c++) {
        if (c + 1 < NP) CLD2(c + 1);

        int b = c & 1;
#pragma unroll
        for (int k = 0; k < 2; k++) {
            uint32_t Ab = s2u(dyn + (b * 2 + k) * CHK);
            uint32_t Bb = s2u(dyn + SMB_BASE + (b * 2 + k) * CHK);
            CHUNK_MMA(Ab, Bb);
        }

        if (c + 1 < NP) CST2((c + 1) & 1);
        __syncthreads();
    }

    if (!skip) {
        float lsum = 0.f, lsq = 0.f;
#pragma unroll
        for (int mt = 0; mt < 2; mt++) {
            int rbase = row0 + m0 + mt * 16 + (lane >> 2);
#pragma unroll
            for (int half = 0; half < 2; half++) {
                int rr = rbase + half * 8;
                if (rr < N_NODES) {
#pragma unroll
                    for (int nt = 0; nt < 4; nt++) {
                        int col = n0 + nt * 8 + (lane & 3) * 2;
                        float v0 = acc[mt][nt][half * 2]     + sparam[col];
                        float v1 = acc[mt][nt][half * 2 + 1] + sparam[col + 1];
                        lsum += v0 + v1;
                        lsq += v0 * v0 + v1 * v1;
                        *(float2*)(out + (size_t)rr * F + col) = make_float2(v0, v1);
                    }
                }
            }
        }
        warp_stats(lsum, lsq, &g_stats[0], &g_stats[1], lane);
    } else {
#pragma unroll
        for (int mt = 0; mt < 2; mt++) {
            int rbase = row0 + m0 + mt * 16 + (lane >> 2);
#pragma unroll
            for (int half = 0; half < 2; half++) {
                int rr = rbase + half * 8;
                if (rr < N_NODES) {
#pragma unroll
                    for (int nt = 0; nt < 4; nt++) {
                        int col = n0 + nt * 8 + (lane & 3) * 2;
                        *(float2*)(out + (size_t)rr * F + col) =
                            make_float2(acc[mt][nt][half * 2], acc[mt][nt][half * 2 + 1]);
                    }
                }
            }
        }
    }
#undef CLD2
#undef CST2
}

// ---------------- fuse: g_h += prelu(ln0(g_o)) (inline finalize) ------------
__global__ void fuse_kernel(const float* __restrict__ lnw,
                            const float* __restrict__ lnb,
                            const float* __restrict__ pw) {
    int i4 = blockIdx.x * blockDim.x + threadIdx.x;
    if (i4 < N_NODES * F / 4) {
        float S = g_stats[0], SS = g_stats[1];
        float inv = 1.0f / ((float)N_NODES * (float)F);
        float m = S * inv;
        float var = fmaxf(SS * inv - m * m, 0.0f);
        float aa = 1.0f / (sqrtf(var) + LN_EPS);
        float pww = pw[0];
        int i = i4 * 4;
        int col = i & (F - 1);
        float4 o = *(const float4*)(g_o + i);
        float4 h = *(const float4*)(g_h + i);
        float t0 = (o.x - m) * aa * lnw[col]     + lnb[col];
        float t1 = (o.y - m) * aa * lnw[col + 1] + lnb[col + 1];
        float t2 = (o.z - m) * aa * lnw[col + 2] + lnb[col + 2];
        float t3 = (o.w - m) * aa * lnw[col + 3] + lnb[col + 3];
        t0 = (t0 >= 0.f) ? t0 : pww * t0;
        t1 = (t1 >= 0.f) ? t1 : pww * t1;
        t2 = (t2 >= 0.f) ? t2 : pww * t2;
        t3 = (t3 >= 0.f) ? t3 : pww * t3;
        *(float4*)(g_h + i) = make_float4(h.x + t0, h.y + t1, h.z + t2, h.w + t3);
    }
}

// ---------------- layer-1 GEMM: pairs 0-3 = g_ms/Wl1, 4-7 = cvt(g_h)/Wr1 ----
__global__ void __launch_bounds__(512) mmagemm_kernel(
    int W0I, int W1I,
    const float* __restrict__ bias,
    int stat_ofs)
{
    extern __shared__ __align__(16) char dyn[];
    float* sparam = (float*)(dyn + SPARAM_OFF);

    float* out = (float*)g_o;

    int tid = threadIdx.x;
    int lane = tid & 31;
    int w = tid >> 5;
    int row0 = blockIdx.x * 128;

    if (tid < F) sparam[tid] = bias[tid];

    int srow = tid >> 2;
    int q = tid & 3;
    size_t arow512 = (size_t)(row0 + srow) * SROWB;
    size_t brow512 = (size_t)srow * SROWB;
    const float* Af = (const float*)g_h + (size_t)(row0 + srow) * F;

    float acc[2][4][4];
#pragma unroll
    for (int i = 0; i < 2; i++)
#pragma unroll
        for (int j = 0; j < 4; j++)
#pragma unroll
            for (int k = 0; k < 4; k++) acc[i][j][k] = 0.0f;

    uint4 ava, avb, bva, bvb;
    float4 af0, af1;

#define LD2(c)                                                                 \
    {                                                                          \
        int p = (c);                                                           \
        int widx, wcb;                                                         \
        if (p < 4) {                                                           \
            const char* ap = g_ms + arow512 + p * 128;                         \
            ava = *(const uint4*)(ap + q * 16);                                \
            avb = *(const uint4*)(ap + 64 + q * 16);                           \
            widx = W0I; wcb = p * 2;                                           \
        } else {                                                               \
            af0 = *(const float4*)(Af + (p - 4) * 32 + q * 4);                 \
            af1 = *(const float4*)(Af + (p - 4) * 32 + 16 + q * 4);            \
            widx = W1I; wcb = (p - 4) * 2;                                     \
        }                                                                      \
        const char* bp = g_ws + (size_t)widx * 65536 + brow512 + wcb * 64;     \
        bva = *(const uint4*)(bp + q * 16);                                    \
        bvb = *(const uint4*)(bp + 64 + q * 16);                               \
    }

#define ST2(b, c)                                                              \
    {                                                                          \
        if ((c) < 4) {                                                         \
            *(uint4*)(dyn + ((b) * 2 + 0) * CHK + srow * PITCHB + q * 16) = ava; \
            *(uint4*)(dyn + ((b) * 2 + 1) * CHK + srow * PITCHB + q * 16) = avb; \
        } else {                                                               \
            uint2 h0, l0, h1, l1;                                              \
            split4(af0, h0, l0);                                               \
            split4(af1, h1, l1);                                               \
            char* a0 = dyn + ((b) * 2 + 0) * CHK + srow * PITCHB + q * 8;      \
            char* a1 = dyn + ((b) * 2 + 1) * CHK + srow * PITCHB + q * 8;      \
            *(uint2*)a0 = h0;  *(uint2*)(a0 + 32) = l0;                        \
            *(uint2*)a1 = h1;  *(uint2*)(a1 + 32) = l1;                        \
        }                                                                      \
        *(uint4*)(dyn + SMB_BASE + ((b) * 2 + 0) * CHK + srow * PITCHB + q * 16) = bva; \
        *(uint4*)(dyn + SMB_BASE + ((b) * 2 + 1) * CHK + srow * PITCHB + q * 16) = bvb; \
    }

    LD2(0);
    ST2(0, 0);
    __syncthreads();

    int wm = w >> 2, wn = w & 3;
    int m0 = wm * 32, n0 = wn * 32;
    uint32_t rsel = (uint32_t)(lane & 15);
    uint32_t kb = (uint32_t)((lane >> 4) * 16);

    for (int c = 0; c < 8; c++) {
        if (c + 1 < 8) LD2(c + 1);

        int b = c & 1;
#pragma unroll
        for (int k = 0; k < 2; k++) {
            uint32_t Ab = s2u(dyn + (b * 2 + k) * CHK);
            uint32_t Bb = s2u(dyn + SMB_BASE + (b * 2 + k) * CHK);
            CHUNK_MMA(Ab, Bb);
        }

        if (c + 1 < 8) ST2((c + 1) & 1, c + 1);
        __syncthreads();
    }

    float lsum = 0.f, lsq = 0.f;
#pragma unroll
    for (int mt = 0; mt < 2; mt++) {
        int rbase = row0 + m0 + mt * 16 + (lane >> 2);
#pragma unroll
        for (int half = 0; half < 2; half++) {
            int rr = rbase + half * 8;
            if (rr < N_NODES) {
#pragma unroll
                for (int nt = 0; nt < 4; nt++) {
                    int col = n0 + nt * 8 + (lane & 3) * 2;
                    float v0 = acc[mt][nt][half * 2]     + sparam[col];
                    float v1 = acc[mt][nt][half * 2 + 1] + sparam[col + 1];
                    lsum += v0 + v1;
                    lsq += v0 * v0 + v1 * v1;
                    *(float2*)(out + (size_t)rr * F + col) = make_float2(v0, v1);
                }
            }
        }
    }
    warp_stats(lsum, lsq, &g_stats[stat_ofs], &g_stats[stat_ofs + 1], lane);
#undef LD2
#undef ST2
}

// ---------------- final LN + PReLU (inline finalize) ----------------
__global__ void apply_kernel(const float* __restrict__ lnw,
                             const float* __restrict__ lnb,
                             const float* __restrict__ pw,
                             float* __restrict__ out) {
    int i = blockIdx.x * blockDim.x + threadIdx.x;
    if (i < N_NODES * F) {
        float S = g_stats[4], SS = g_stats[5];
        float inv = 1.0f / ((float)N_NODES * (float)F);
        float m = S * inv;
        float var = fmaxf(SS * inv - m * m, 0.0f);
        float a = 1.0f / (sqrtf(var) + LN_EPS);
        int col = i & (F - 1);
        float t = (g_o[i] - m) * a * lnw[col] + lnb[col];
        out[i] = (t >= 0.f) ? t : pw[0] * t;
    }
}

// ---------------- launch ----------------
extern "C" void kernel_launch(void* const* d_in, const int* in_sizes, int n_in,
                              void* d_out, int out_size) {
    const float* x      = (const float*)d_in[0];
    const void*  ei     = d_in[1];
    const float* Wl0    = (const float*)d_in[2];
    const float* bl0    = (const float*)d_in[3];
    const float* Wr0    = (const float*)d_in[4];
    const float* lnw0   = (const float*)d_in[5];
    const float* lnb0   = (const float*)d_in[6];
    const float* pw0    = (const float*)d_in[7];
    const float* skipW0 = (const float*)d_in[8];
    const float* Wl1    = (const float*)d_in[9];
    const float* bl1    = (const float*)d_in[10];
    const float* Wr1    = (const float*)d_in[11];
    const float* lnw1   = (const float*)d_in[12];
    const float* lnb1   = (const float*)d_in[13];
    const float* pw1    = (const float*)d_in[14];

    int wblocks = (N_NODES * 32 + 255) / 256;            // 6250

    cudaFuncSetAttribute(combogemm_kernel,
                         cudaFuncAttributeMaxDynamicSharedMemorySize, DYN_TOTAL);
    cudaFuncSetAttribute(mmagemm_kernel,
                         cudaFuncAttributeMaxDynamicSharedMemorySize, DYN_TOTAL);

    // 1: zero/detect, 2: CSR build + overlapped x/w pre-split
    prep0_kernel<<<NBLK, 256>>>(ei);
    csr_kernel<<<CSR_BLOCKS, 256>>>(ei, x, Wl0, Wr0, skipW0, Wl1, Wr1);

    // 3: gather layer-0 mean, 4: SAGE0 GEMM + skip GEMM combined
    gather_kernel<<<wblocks, 256>>>(x);
    combogemm_kernel<<<2 * GB, 512, DYN_TOTAL>>>(bl0);
    // 5: g_h = skip + prelu(ln0(g_o))
    fuse_kernel<<<(N_NODES * F / 4 + 255) / 256, 256>>>(lnw0, lnb0, pw0);

    // 6: gather layer-1 mean, 7: SAGE1 GEMM
    gather_kernel<<<wblocks, 256>>>(nullptr);            // reads g_h
    mmagemm_kernel<<<GB, 512, DYN_TOTAL>>>(3, 4, bl1, 4);
    // 8: final LN + PReLU
    apply_kernel<<<(N_NODES * F + 255) / 256, 256>>>(lnw1, lnb1, pw1, (float*)d_out);
}

// round 17
// speedup vs baseline: 1.0918x; 1.0918x over previous
#include <cuda_runtime.h>
#include <cuda_bf16.h>
#include <cstdint>

#define N_NODES 50000
#define N_EDGES 800000
#define F 128
#define LN_EPS 1e-5f
#define NBLK 196            // (N_NODES+255)/256
#define NPAD (N_NODES + 128)
#define SROWB 512           // bytes per split row (8 chunks x [32B hi | 32B lo])
#define CSR_BLOCKS 592      // 4 per SM; co-resident for grid barrier
#define GB 391              // GEMM tiles: (N_NODES+127)/128

#define PITCHB 80
#define CHK (128 * PITCHB)           // one K-16 chunk tile (10240 B)
#define SMB_BASE (4 * CHK)
#define SPARAM_OFF (8 * CHK)
#define RBUF_OFF (SPARAM_OFF + 512)
#define DYN_TOTAL (RBUF_OFF + 512 * 8)

// ---------------- scratch (__device__ globals only) ----------------
__device__ int   g_is64;
__device__ int   g_count[N_NODES];
__device__ int   g_start[N_NODES + 1];
__device__ int   g_cursor[N_NODES];
__device__ int   g_bsum[NBLK];
__device__ int   g_boff[NBLK];
__device__ int   g_esrc[N_EDGES];
__device__ float g_invdeg[N_NODES];
__device__ char  g_ws[5 * 65536];                    // split weights (tile layout)
__device__ char  g_xs[(size_t)NPAD * SROWB];         // split x
__device__ char  g_ms[(size_t)NPAD * SROWB];         // split neighbor-mean
__device__ float g_h[(size_t)NPAD * F];              // skip out, then layer-1 input
__device__ float g_o[(size_t)NPAD * F];              // raw SAGE out (pre-LN)
__device__ float g_stats[8];
__device__ int   g_barcnt, g_barphase;               // csr barrier

// ---------------- helpers ----------------
__device__ __forceinline__ uint32_t s2u(const void* p) {
    uint32_t a;
    asm("{ .reg .u64 t; cvta.to.shared.u64 t, %1; cvt.u32.u64 %0, t; }"
        : "=r"(a) : "l"(p));
    return a;
}
__device__ __forceinline__ uint32_t pkbf(float a, float b) {
    uint32_t r;
    asm("cvt.rn.bf16x2.f32 %0, %1, %2;" : "=r"(r) : "f"(b), "f"(a));
    return r;
}
__device__ __forceinline__ void ldsm4(uint32_t addr, uint32_t* r) {
    asm volatile("ldmatrix.sync.aligned.m8n8.x4.shared.b16 {%0,%1,%2,%3}, [%4];"
                 : "=r"(r[0]), "=r"(r[1]), "=r"(r[2]), "=r"(r[3]) : "r"(addr));
}
__device__ __forceinline__ void bmma(float* d, const uint32_t* a, uint32_t b0, uint32_t b1) {
    asm volatile("mma.sync.aligned.m16n8k16.row.col.f32.bf16.bf16.f32 "
                 "{%0,%1,%2,%3}, {%4,%5,%6,%7}, {%8,%9}, {%0,%1,%2,%3};"
                 : "+f"(d[0]), "+f"(d[1]), "+f"(d[2]), "+f"(d[3])
                 : "r"(a[0]), "r"(a[1]), "r"(a[2]), "r"(a[3]), "r"(b0), "r"(b1));
}
__device__ __forceinline__ void split4(float4 v, uint2& hi, uint2& lo) {
    float h0 = __bfloat162float(__float2bfloat16_rn(v.x));
    float h1 = __bfloat162float(__float2bfloat16_rn(v.y));
    float h2 = __bfloat162float(__float2bfloat16_rn(v.z));
    float h3 = __bfloat162float(__float2bfloat16_rn(v.w));
    hi = make_uint2(pkbf(h0, h1), pkbf(h2, h3));
    lo = make_uint2(pkbf(v.x - h0, v.y - h1), pkbf(v.z - h2, v.w - h3));
}
__device__ __forceinline__ int ld_idx(const void* ei, long long pos, int is64) {
    if (is64) return (int)((const long long*)ei)[pos];
    return ((const int*)ei)[pos];
}
__device__ __forceinline__ void gridbar(int ph) {
    __syncthreads();
    if (threadIdx.x == 0) {
        __threadfence();
        int v = atomicAdd(&g_barcnt, 1) + 1;
        if (v == CSR_BLOCKS * ph) atomicExch(&g_barphase, ph);
        while (atomicAdd(&g_barphase, 0) < ph) __nanosleep(32);
    }
    __syncthreads();
}

// x-split / w-split helpers
__device__ __forceinline__ void do_xsplit(const float* __restrict__ x, int t) {
    int row = t >> 5, lane = t & 31;
    float4 v = *(const float4*)(x + (size_t)row * F + lane * 4);
    uint2 hi, lo;
    split4(v, hi, lo);
    char* dst = g_xs + (size_t)row * SROWB + (lane >> 2) * 64 + (lane & 3) * 8;
    *(uint2*)dst = hi;
    *(uint2*)(dst + 32) = lo;
}
__device__ __forceinline__ void do_wsplit(const float* __restrict__ W0, const float* __restrict__ W1,
                                          const float* __restrict__ W2, const float* __restrict__ W3,
                                          const float* __restrict__ W4, int t) {
    int mat = t >> 12;
    int rem = t & 4095;
    int row = rem >> 5, lane = rem & 31;
    const float* W = (mat == 0) ? W0 : (mat == 1) ? W1 : (mat == 2) ? W2
                     : (mat == 3) ? W3 : W4;
    float4 v = *(const float4*)(W + row * F + lane * 4);
    uint2 hi, lo;
    split4(v, hi, lo);
    char* dst = g_ws + (size_t)mat * 65536 + row * SROWB + (lane >> 2) * 64 + (lane & 3) * 8;
    *(uint2*)dst = hi;
    *(uint2*)(dst + 32) = lo;
}

// ---------------- prep0: zero counters + dtype probe + barrier reset --------
__global__ void prep0_kernel(const void* ei) {
    int i = blockIdx.x * blockDim.x + threadIdx.x;
    if (i < N_NODES) { g_count[i] = 0; g_cursor[i] = 0; }
    if (blockIdx.x == 0) {
        __shared__ int nz;
        int tid = threadIdx.x;
        if (tid == 0) nz = 0;
        __syncthreads();
        int v = ((const int*)ei)[2 * tid + 1];
        if (v != 0) atomicAdd(&nz, 1);
        __syncthreads();
        if (tid == 0) {
            g_is64 = (nz == 0) ? 1 : 0;
            g_barcnt = 0; g_barphase = 0;
        }
        if (tid < 8) g_stats[tid] = 0.0f;
    }
}

// ---------------- persistent CSR build + overlapped pre-splits --------------
__global__ void __launch_bounds__(256) csr_kernel(
    const void* ei, const float* __restrict__ x,
    const float* __restrict__ W0, const float* __restrict__ W1,
    const float* __restrict__ W2, const float* __restrict__ W3,
    const float* __restrict__ W4) {
    __shared__ int sh[256];
    int tid = threadIdx.x;
    int b = blockIdx.x;
    int is64 = g_is64;

    // phase 0: x-split + w-split + histogram (independent work streams)
    for (int t = b * 256 + tid; t < N_NODES * 32; t += CSR_BLOCKS * 256)
        do_xsplit(x, t);
    for (int t = b * 256 + tid; t < 5 * 4096; t += CSR_BLOCKS * 256)
        do_wsplit(W0, W1, W2, W3, W4, t);
    for (int e = b * 256 + tid; e < N_EDGES; e += CSR_BLOCKS * 256) {
        int d = ld_idx(ei, (long long)N_EDGES + e, is64);
        atomicAdd(&g_count[d], 1);
    }
    gridbar(1);

    if (b < NBLK) {
        int i = b * 256 + tid;
        int c = (i < N_NODES) ? g_count[i] : 0;
        sh[tid] = c;
        __syncthreads();
#pragma unroll
        for (int s = 128; s > 0; s >>= 1) {
            if (tid < s) sh[tid] += sh[tid + s];
            __syncthreads();
        }
        if (tid == 0) g_bsum[b] = sh[0];
    }
    gridbar(2);

    if (b == 0) {
        int v = (tid < NBLK) ? g_bsum[tid] : 0;
        sh[tid] = v;
        __syncthreads();
#pragma unroll
        for (int off = 1; off < 256; off <<= 1) {
            int u = (tid >= off) ? sh[tid - off] : 0;
            __syncthreads();
            sh[tid] += u;
            __syncthreads();
        }
        if (tid < NBLK) g_boff[tid] = sh[tid] - v;
        if (tid == 0) g_start[N_NODES] = N_EDGES;
    }
    gridbar(3);

    if (b < NBLK) {
        int i = b * 256 + tid;
        int c = (i < N_NODES) ? g_count[i] : 0;
        sh[tid] = c;
        __syncthreads();
#pragma unroll
        for (int off = 1; off < 256; off <<= 1) {
            int u = (tid >= off) ? sh[tid - off] : 0;
            __syncthreads();
            sh[tid] += u;
            __syncthreads();
        }
        if (i < N_NODES) {
            g_start[i] = sh[tid] - c + g_boff[b];
            g_invdeg[i] = 1.0f / fmaxf((float)c, 1.0f);
        }
    }
    gridbar(4);

    for (int e = b * 256 + tid; e < N_EDGES; e += CSR_BLOCKS * 256) {
        int d = ld_idx(ei, (long long)N_EDGES + e, is64);
        int s = ld_idx(ei, (long long)e, is64);
        int pos = atomicAdd(&g_cursor[d], 1);
        g_esrc[g_start[d] + pos] = s;
    }
}

// ---------------- gather-mean: warp per node, emits split form ----------------
__global__ void gather_kernel(const float* __restrict__ hin) {
    const float* h = hin ? hin : (const float*)g_h;
    int n = (blockIdx.x * blockDim.x + threadIdx.x) >> 5;
    int lane = threadIdx.x & 31;
    if (n >= N_NODES) return;
    int e = g_start[n];
    int end = g_start[n + 1];
    float4 acc0 = make_float4(0.f, 0.f, 0.f, 0.f);
    float4 acc1 = make_float4(0.f, 0.f, 0.f, 0.f);
    for (; e + 1 < end; e += 2) {
        int s0 = g_esrc[e];
        int s1 = g_esrc[e + 1];
        float4 v0 = *(const float4*)(h + (size_t)s0 * F + lane * 4);
        float4 v1 = *(const float4*)(h + (size_t)s1 * F + lane * 4);
        acc0.x += v0.x; acc0.y += v0.y; acc0.z += v0.z; acc0.w += v0.w;
        acc1.x += v1.x; acc1.y += v1.y; acc1.z += v1.z; acc1.w += v1.w;
    }
    if (e < end) {
        int s0 = g_esrc[e];
        float4 v0 = *(const float4*)(h + (size_t)s0 * F + lane * 4);
        acc0.x += v0.x; acc0.y += v0.y; acc0.z += v0.z; acc0.w += v0.w;
    }
    float id = g_invdeg[n];
    acc0.x = (acc0.x + acc1.x) * id;
    acc0.y = (acc0.y + acc1.y) * id;
    acc0.z = (acc0.z + acc1.z) * id;
    acc0.w = (acc0.w + acc1.w) * id;
    uint2 hi, lo;
    split4(acc0, hi, lo);
    char* dst = g_ms + (size_t)n * SROWB + (lane >> 2) * 64 + (lane & 3) * 8;
    *(uint2*)dst = hi;
    *(uint2*)(dst + 32) = lo;
}

// ---------------- compute macro: one K-16 chunk from smem tile --------------
#define CHUNK_MMA(Ab, Bb)                                                      \
    {                                                                          \
        uint32_t aaddr0 = (Ab) + (m0 + rsel) * PITCHB + kb;                    \
        uint32_t aaddr1 = aaddr0 + 16 * PITCHB;                                \
        uint32_t baddr0 = (Bb) + (n0 + rsel) * PITCHB + kb;                    \
        uint32_t baddr1 = baddr0 + 16 * PITCHB;                                \
        uint32_t ahi[2][4], alo[2][4], bhi[2][4], blo[2][4];                   \
        ldsm4(aaddr0, ahi[0]);  ldsm4(aaddr1, ahi[1]);                         \
        ldsm4(baddr0, bhi[0]);  ldsm4(baddr1, bhi[1]);                         \
        ldsm4(aaddr0 + 32, alo[0]);  ldsm4(aaddr1 + 32, alo[1]);               \
        ldsm4(baddr0 + 32, blo[0]);  ldsm4(baddr1 + 32, blo[1]);               \
        _Pragma("unroll")                                                      \
        for (int mt = 0; mt < 2; mt++)                                         \
            _Pragma("unroll")                                                  \
            for (int nt = 0; nt < 4; nt++)                                     \
                bmma(acc[mt][nt], ahi[mt], bhi[nt >> 1][nt & 1],               \
                     bhi[nt >> 1][(nt & 1) + 2]);                              \
        _Pragma("unroll")                                                      \
        for (int mt = 0; mt < 2; mt++)                                         \
            _Pragma("unroll")                                                  \
            for (int nt = 0; nt < 4; nt++)                                     \
                bmma(acc[mt][nt], ahi[mt], blo[nt >> 1][nt & 1],               \
                     blo[nt >> 1][(nt & 1) + 2]);                              \
        _Pragma("unroll")                                                      \
        for (int mt = 0; mt < 2; mt++)                                         \
            _Pragma("unroll")                                                  \
            for (int nt = 0; nt < 4; nt++)                                     \
                bmma(acc[mt][nt], alo[mt], bhi[nt >> 1][nt & 1],               \
                     bhi[nt >> 1][(nt & 1) + 2]);                              \
    }

// ---------------- combined GEMM: SAGE0 (stats) + skip GEMM in one grid ------
__global__ void __launch_bounds__(512) combogemm_kernel(const float* __restrict__ bias)
{
    extern __shared__ __align__(16) char dyn[];
    float* sparam = (float*)(dyn + SPARAM_OFF);
    float2* rbuf = (float2*)(dyn + RBUF_OFF);

    int tid = threadIdx.x;
    int lane = tid & 31;
    int w = tid >> 5;
    bool skip = blockIdx.x >= GB;
    int row0 = (skip ? blockIdx.x - GB : blockIdx.x) * 128;
    int NP = skip ? 4 : 8;
    float* out = skip ? (float*)g_h : (float*)g_o;

    if (tid < F) sparam[tid] = bias[tid];

    int srow = tid >> 2;
    int q = tid & 3;
    size_t arow512 = (size_t)(row0 + srow) * SROWB;
    size_t brow512 = (size_t)srow * SROWB;

    float acc[2][4][4];
#pragma unroll
    for (int i = 0; i < 2; i++)
#pragma unroll
        for (int j = 0; j < 4; j++)
#pragma unroll
            for (int k = 0; k < 4; k++) acc[i][j][k] = 0.0f;

    uint4 ava, avb, bva, bvb;

#define CLD2(c)                                                                \
    {                                                                          \
        int p = (c);                                                           \
        const char* ap;                                                        \
        int widx, wcb;                                                         \
        if (skip) { ap = g_xs + arow512 + p * 128; widx = 2; wcb = p * 2; }    \
        else if (p < 4) { ap = g_ms + arow512 + p * 128; widx = 0; wcb = p * 2; } \
        else { ap = g_xs + arow512 + (p - 4) * 128; widx = 1; wcb = (p - 4) * 2; } \
        ava = *(const uint4*)(ap + q * 16);                                    \
        avb = *(const uint4*)(ap + 64 + q * 16);                               \
        const char* bp = g_ws + (size_t)widx * 65536 + brow512 + wcb * 64;     \
        bva = *(const uint4*)(bp + q * 16);                                    \
        bvb = *(const uint4*)(bp + 64 + q * 16);                               \
    }

#define CST2(b)                                                                \
    {                                                                          \
        *(uint4*)(dyn + ((b) * 2 + 0) * CHK + srow * PITCHB + q * 16) = ava;   \
        *(uint4*)(dyn + ((b) * 2 + 1) * CHK + srow * PITCHB + q * 16) = avb;   \
        *(uint4*)(dyn + SMB_BASE + ((b) * 2 + 0) * CHK + srow * PITCHB + q * 16) = bva; \
        *(uint4*)(dyn + SMB_BASE + ((b) * 2 + 1) * CHK + srow * PITCHB + q * 16) = bvb; \
    }

    CLD2(0);
    CST2(0);
    __syncthreads();

    int wm = w >> 2, wn = w & 3;
    int m0 = wm * 32, n0 = wn * 32;
    uint32_t rsel = (uint32_t)(lane & 15);
    uint32_t kb = (uint32_t)((lane >> 4) * 16);

    for (int c = 0; c < NP; c++) {
        if (c + 1 < NP) CLD2(c + 1);

        int b = c & 1;
#pragma unroll
        for (int k = 0; k < 2; k++) {
            uint32_t Ab = s2u(dyn + (b * 2 + k) * CHK);
            uint32_t Bb = s2u(dyn + SMB_BASE + (b * 2 + k) * CHK);
            CHUNK_MMA(Ab, Bb);
        }

        if (c + 1 < NP) CST2((c + 1) & 1);
        __syncthreads();
    }

    if (!skip) {
        float lsum = 0.f, lsq = 0.f;
#pragma unroll
        for (int mt = 0; mt < 2; mt++) {
            int rbase = row0 + m0 + mt * 16 + (lane >> 2);
#pragma unroll
            for (int half = 0; half < 2; half++) {
                int rr = rbase + half * 8;
                if (rr < N_NODES) {
#pragma unroll
                    for (int nt = 0; nt < 4; nt++) {
                        int col = n0 + nt * 8 + (lane & 3) * 2;
                        float v0 = acc[mt][nt][half * 2]     + sparam[col];
                        float v1 = acc[mt][nt][half * 2 + 1] + sparam[col + 1];
                        lsum += v0 + v1;
                        lsq += v0 * v0 + v1 * v1;
                        *(float2*)(out + (size_t)rr * F + col) = make_float2(v0, v1);
                    }
                }
            }
        }
        rbuf[tid] = make_float2(lsum, lsq);
        __syncthreads();
        for (int s = 256; s > 0; s >>= 1) {
            if (tid < s) {
                rbuf[tid].x += rbuf[tid + s].x;
                rbuf[tid].y += rbuf[tid + s].y;
            }
            __syncthreads();
        }
        if (tid == 0) {
            atomicAdd(&g_stats[0], rbuf[0].x);
            atomicAdd(&g_stats[1], rbuf[0].y);
        }
    } else {
#pragma unroll
        for (int mt = 0; mt < 2; mt++) {
            int rbase = row0 + m0 + mt * 16 + (lane >> 2);
#pragma unroll
            for (int half = 0; half < 2; half++) {
                int rr = rbase + half * 8;
                if (rr < N_NODES) {
#pragma unroll
                    for (int nt = 0; nt < 4; nt++) {
                        int col = n0 + nt * 8 + (lane & 3) * 2;
                        *(float2*)(out + (size_t)rr * F + col) =
                            make_float2(acc[mt][nt][half * 2], acc[mt][nt][half * 2 + 1]);
                    }
                }
            }
        }
    }
#undef CLD2
#undef CST2
}

// ---------------- fuse: g_h += prelu(ln0(g_o)) (inline finalize) ------------
__global__ void fuse_kernel(const float* __restrict__ lnw,
                            const float* __restrict__ lnb,
                            const float* __restrict__ pw) {
    int i4 = blockIdx.x * blockDim.x + threadIdx.x;
    if (i4 < N_NODES * F / 4) {
        float S = g_stats[0], SS = g_stats[1];
        float inv = 1.0f / ((float)N_NODES * (float)F);
        float m = S * inv;
        float var = fmaxf(SS * inv - m * m, 0.0f);
        float aa = 1.0f / (sqrtf(var) + LN_EPS);
        float pww = pw[0];
        int i = i4 * 4;
        int col = i & (F - 1);
        float4 o = *(const float4*)(g_o + i);
        float4 h = *(const float4*)(g_h + i);
        float t0 = (o.x - m) * aa * lnw[col]     + lnb[col];
        float t1 = (o.y - m) * aa * lnw[col + 1] + lnb[col + 1];
        float t2 = (o.z - m) * aa * lnw[col + 2] + lnb[col + 2];
        float t3 = (o.w - m) * aa * lnw[col + 3] + lnb[col + 3];
        t0 = (t0 >= 0.f) ? t0 : pww * t0;
        t1 = (t1 >= 0.f) ? t1 : pww * t1;
        t2 = (t2 >= 0.f) ? t2 : pww * t2;
        t3 = (t3 >= 0.f) ? t3 : pww * t3;
        *(float4*)(g_h + i) = make_float4(h.x + t0, h.y + t1, h.z + t2, h.w + t3);
    }
}

// ---------------- layer-1 GEMM: pairs 0-3 = g_ms/Wl1, 4-7 = cvt(g_h)/Wr1 ----
__global__ void __launch_bounds__(512) mmagemm_kernel(
    int W0I, int W1I,
    const float* __restrict__ bias,
    int stat_ofs)
{
    extern __shared__ __align__(16) char dyn[];
    float* sparam = (float*)(dyn + SPARAM_OFF);
    float2* rbuf = (float2*)(dyn + RBUF_OFF);

    float* out = (float*)g_o;

    int tid = threadIdx.x;
    int lane = tid & 31;
    int w = tid >> 5;
    int row0 = blockIdx.x * 128;

    if (tid < F) sparam[tid] = bias[tid];

    int srow = tid >> 2;
    int q = tid & 3;
    size_t arow512 = (size_t)(row0 + srow) * SROWB;
    size_t brow512 = (size_t)srow * SROWB;
    const float* Af = (const float*)g_h + (size_t)(row0 + srow) * F;

    float acc[2][4][4];
#pragma unroll
    for (int i = 0; i < 2; i++)
#pragma unroll
        for (int j = 0; j < 4; j++)
#pragma unroll
            for (int k = 0; k < 4; k++) acc[i][j][k] = 0.0f;

    uint4 ava, avb, bva, bvb;
    float4 af0, af1;

#define LD2(c)                                                                 \
    {                                                                          \
        int p = (c);                                                           \
        int widx, wcb;                                                         \
        if (p < 4) {                                                           \
            const char* ap = g_ms + arow512 + p * 128;                         \
            ava = *(const uint4*)(ap + q * 16);                                \
            avb = *(const uint4*)(ap + 64 + q * 16);                           \
            widx = W0I; wcb = p * 2;                                           \
        } else {                                                               \
            af0 = *(const float4*)(Af + (p - 4) * 32 + q * 4);                 \
            af1 = *(const float4*)(Af + (p - 4) * 32 + 16 + q * 4);            \
            widx = W1I; wcb = (p - 4) * 2;                                     \
        }                                                                      \
        const char* bp = g_ws + (size_t)widx * 65536 + brow512 + wcb * 64;     \
        bva = *(const uint4*)(bp + q * 16);                                    \
        bvb = *(const uint4*)(bp + 64 + q * 16);                               \
    }

#define ST2(b, c)                                                              \
    {                                                                          \
        if ((c) < 4) {                                                         \
            *(uint4*)(dyn + ((b) * 2 + 0) * CHK + srow * PITCHB + q * 16) = ava; \
            *(uint4*)(dyn + ((b) * 2 + 1) * CHK + srow * PITCHB + q * 16) = avb; \
        } else {                                                               \
            uint2 h0, l0, h1, l1;                                              \
            split4(af0, h0, l0);                                               \
            split4(af1, h1, l1);                                               \
            char* a0 = dyn + ((b) * 2 + 0) * CHK + srow * PITCHB + q * 8;      \
            char* a1 = dyn + ((b) * 2 + 1) * CHK + srow * PITCHB + q * 8;      \
            *(uint2*)a0 = h0;  *(uint2*)(a0 + 32) = l0;                        \
            *(uint2*)a1 = h1;  *(uint2*)(a1 + 32) = l1;                        \
        }                                                                      \
        *(uint4*)(dyn + SMB_BASE + ((b) * 2 + 0) * CHK + srow * PITCHB + q * 16) = bva; \
        *(uint4*)(dyn + SMB_BASE + ((b) * 2 + 1) * CHK + srow * PITCHB + q * 16) = bvb; \
    }

    LD2(0);
    ST2(0, 0);
    __syncthreads();

    int wm = w >> 2, wn = w & 3;
    int m0 = wm * 32, n0 = wn * 32;
    uint32_t rsel = (uint32_t)(lane & 15);
    uint32_t kb = (uint32_t)((lane >> 4) * 16);

    for (int c = 0; c < 8; c++) {
        if (c + 1 < 8) LD2(c + 1);

        int b = c & 1;
#pragma unroll
        for (int k = 0; k < 2; k++) {
            uint32_t Ab = s2u(dyn + (b * 2 + k) * CHK);
            uint32_t Bb = s2u(dyn + SMB_BASE + (b * 2 + k) * CHK);
            CHUNK_MMA(Ab, Bb);
        }

        if (c + 1 < 8) ST2((c + 1) & 1, c + 1);
        __syncthreads();
    }

    float lsum = 0.f, lsq = 0.f;
#pragma unroll
    for (int mt = 0; mt < 2; mt++) {
        int rbase = row0 + m0 + mt * 16 + (lane >> 2);
#pragma unroll
        for (int half = 0; half < 2; half++) {
            int rr = rbase + half * 8;
            if (rr < N_NODES) {
#pragma unroll
                for (int nt = 0; nt < 4; nt++) {
                    int col = n0 + nt * 8 + (lane & 3) * 2;
                    float v0 = acc[mt][nt][half * 2]     + sparam[col];
                    float v1 = acc[mt][nt][half * 2 + 1] + sparam[col + 1];
                    lsum += v0 + v1;
                    lsq += v0 * v0 + v1 * v1;
                    *(float2*)(out + (size_t)rr * F + col) = make_float2(v0, v1);
                }
            }
        }
    }
    rbuf[tid] = make_float2(lsum, lsq);
    __syncthreads();
    for (int s = 256; s > 0; s >>= 1) {
        if (tid < s) {
            rbuf[tid].x += rbuf[tid + s].x;
            rbuf[tid].y += rbuf[tid + s].y;
        }
        __syncthreads();
    }
    if (tid == 0) {
        atomicAdd(&g_stats[stat_ofs], rbuf[0].x);
        atomicAdd(&g_stats[stat_ofs + 1], rbuf[0].y);
    }
#undef LD2
#undef ST2
}

// ---------------- final LN + PReLU (vectorized, inline finalize) ------------
__global__ void apply_kernel(const float* __restrict__ lnw,
                             const float* __restrict__ lnb,
                             const float* __restrict__ pw,
                             float* __restrict__ out) {
    int i4 = blockIdx.x * blockDim.x + threadIdx.x;
    if (i4 < N_NODES * F / 4) {
        float S = g_stats[4], SS = g_stats[5];
        float inv = 1.0f / ((float)N_NODES * (float)F);
        float m = S * inv;
        float var = fmaxf(SS * inv - m * m, 0.0f);
        float aa = 1.0f / (sqrtf(var) + LN_EPS);
        float pww = pw[0];
        int i = i4 * 4;
        int col = i & (F - 1);
        float4 o = *(const float4*)(g_o + i);
        float t0 = (o.x - m) * aa * lnw[col]     + lnb[col];
        float t1 = (o.y - m) * aa * lnw[col + 1] + lnb[col + 1];
        float t2 = (o.z - m) * aa * lnw[col + 2] + lnb[col + 2];
        float t3 = (o.w - m) * aa * lnw[col + 3] + lnb[col + 3];
        t0 = (t0 >= 0.f) ? t0 : pww * t0;
        t1 = (t1 >= 0.f) ? t1 : pww * t1;
        t2 = (t2 >= 0.f) ? t2 : pww * t2;
        t3 = (t3 >= 0.f) ? t3 : pww * t3;
        *(float4*)(out + i) = make_float4(t0, t1, t2, t3);
    }
}

// ---------------- launch ----------------
extern "C" void kernel_launch(void* const* d_in, const int* in_sizes, int n_in,
                              void* d_out, int out_size) {
    const float* x      = (const float*)d_in[0];
    const void*  ei     = d_in[1];
    const float* Wl0    = (const float*)d_in[2];
    const float* bl0    = (const float*)d_in[3];
    const float* Wr0    = (const float*)d_in[4];
    const float* lnw0   = (const float*)d_in[5];
    const float* lnb0   = (const float*)d_in[6];
    const float* pw0    = (const float*)d_in[7];
    const float* skipW0 = (const float*)d_in[8];
    const float* Wl1    = (const float*)d_in[9];
    const float* bl1    = (const float*)d_in[10];
    const float* Wr1    = (const float*)d_in[11];
    const float* lnw1   = (const float*)d_in[12];
    const float* lnb1   = (const float*)d_in[13];
    const float* pw1    = (const float*)d_in[14];

    int wblocks = (N_NODES * 32 + 255) / 256;            // 6250

    cudaFuncSetAttribute(combogemm_kernel,
                         cudaFuncAttributeMaxDynamicSharedMemorySize, DYN_TOTAL);
    cudaFuncSetAttribute(mmagemm_kernel,
                         cudaFuncAttributeMaxDynamicSharedMemorySize, DYN_TOTAL);

    // 1: zero/detect, 2: CSR build + overlapped x/w pre-split
    prep0_kernel<<<NBLK, 256>>>(ei);
    csr_kernel<<<CSR_BLOCKS, 256>>>(ei, x, Wl0, Wr0, skipW0, Wl1, Wr1);

    // 3: gather layer-0 mean, 4: SAGE0 GEMM + skip GEMM combined
    gather_kernel<<<wblocks, 256>>>(x);
    combogemm_kernel<<<2 * GB, 512, DYN_TOTAL>>>(bl0);
    // 5: g_h = skip + prelu(ln0(g_o))
    fuse_kernel<<<(N_NODES * F / 4 + 255) / 256, 256>>>(lnw0, lnb0, pw0);

    // 6: gather layer-1 mean, 7: SAGE1 GEMM
    gather_kernel<<<wblocks, 256>>>(nullptr);            // reads g_h
    mmagemm_kernel<<<GB, 512, DYN_TOTAL>>>(3, 4, bl1, 4);
    // 8: final LN + PReLU (vectorized)
    apply_kernel<<<(N_NODES * F / 4 + 255) / 256, 256>>>(lnw1, lnb1, pw1, (float*)d_out);
}